// round 1
// baseline (speedup 1.0000x reference)
#include <cuda_runtime.h>
#include <cstdint>

// ---------------------------------------------------------------------------
// TemporalGCN: conv1+relu+pool -> conv2+relu+pool -> GCN1 -> GCN2 -> mean -> fc
// B=1024, C_IN=9, T=2048, RT=512, HID=128, OUT=64
//
// GCN trick: aggregation is linear => combine neighbors on the GEMM input side.
// GCN2 epilogue: relu + per-batch column partial sums (h2 never materialized).
// GEMMs use fma.rn.f32x2 (packed fp32, exact) for 2x FFMA throughput.
// ---------------------------------------------------------------------------

#define B_      1024
#define T_      2048
#define T1_     1024
#define RT_     512
#define HID_    128

static __device__ float g_o1[(size_t)B_ * 16 * T1_];     // conv1 out  (67 MB)
static __device__ float g_o2[(size_t)B_ * 32 * RT_];     // conv2 out  (67 MB)
static __device__ float g_h1[(size_t)B_ * RT_ * HID_];   // gcn1 out   (268 MB)
static __device__ float g_bsum[(size_t)B_ * 4 * HID_];   // per-(batch,chunk) colsums

__device__ __forceinline__ unsigned long long dup2(float a) {
    unsigned ai = __float_as_uint(a);
    unsigned long long r;
    asm("mov.b64 %0, {%1, %1};" : "=l"(r) : "r"(ai));
    return r;
}
#define FFMA2(d, a, b) asm("fma.rn.f32x2 %0, %1, %2, %0;" : "+l"(d) : "l"(a), "l"(b))

#define RS2 0.70710678118654752f   // 2^-1/2
#define RS3 0.57735026918962576f   // 3^-1/2

// ---------------------------------------------------------------------------
// conv1 + relu + maxpool2 : x[B,9,2048] -> g_o1[B,16,1024]
// grid (1024, 8), 128 threads; each thread computes one pooled t' for all 16 co
// ---------------------------------------------------------------------------
__global__ void conv1_kernel(const float* __restrict__ x,
                             const float* __restrict__ w,
                             const float* __restrict__ bias) {
    __shared__ float xs[9][260];
    __shared__ float ws[16 * 9 * 5];
    __shared__ float bs[16];
    const int b = blockIdx.x, t0 = blockIdx.y * 128, tid = threadIdx.x;

    for (int e = tid; e < 720; e += 128) ws[e] = w[e];
    if (tid < 16) bs[tid] = bias[tid];

    const float* xb = x + (size_t)b * 9 * T_;
    const int base = 2 * t0 - 2;
    for (int e = tid; e < 9 * 260; e += 128) {
        int ci = e / 260, j = e % 260;
        int t = base + j;
        xs[ci][j] = (t >= 0 && t < T_) ? xb[ci * T_ + t] : 0.f;
    }
    __syncthreads();

    const int lt = tid;
    float xv[9][6];
#pragma unroll
    for (int ci = 0; ci < 9; ci++)
#pragma unroll
        for (int j = 0; j < 6; j++) xv[ci][j] = xs[ci][2 * lt + j];

    float* ob = g_o1 + (size_t)b * 16 * T1_ + (t0 + lt);
#pragma unroll
    for (int co = 0; co < 16; co++) {
        float a0 = 0.f, a1 = 0.f;
#pragma unroll
        for (int ci = 0; ci < 9; ci++)
#pragma unroll
            for (int k = 0; k < 5; k++) {
                float wv = ws[(co * 9 + ci) * 5 + k];
                a0 += wv * xv[ci][k];
                a1 += wv * xv[ci][k + 1];
            }
        ob[(size_t)co * T1_] = fmaxf(fmaxf(a0, a1) + bs[co], 0.f);
    }
}

// ---------------------------------------------------------------------------
// conv2 + relu + maxpool2 : g_o1[B,16,1024] -> g_o2[B,32,512]
// grid (1024, 4), 128 threads
// ---------------------------------------------------------------------------
__global__ void conv2_kernel(const float* __restrict__ w,
                             const float* __restrict__ bias) {
    __shared__ float xs[16][260];
    __shared__ float ws[32 * 16 * 5];
    __shared__ float bs[32];
    const int b = blockIdx.x, t0 = blockIdx.y * 128, tid = threadIdx.x;

    for (int e = tid; e < 2560; e += 128) ws[e] = w[e];
    if (tid < 32) bs[tid] = bias[tid];

    const float* xb = g_o1 + (size_t)b * 16 * T1_;
    const int base = 2 * t0 - 2;
    for (int e = tid; e < 16 * 260; e += 128) {
        int ci = e / 260, j = e % 260;
        int t = base + j;
        xs[ci][j] = (t >= 0 && t < T1_) ? xb[ci * T1_ + t] : 0.f;
    }
    __syncthreads();

    const int lt = tid;
    float a0[32], a1[32];
#pragma unroll
    for (int co = 0; co < 32; co++) { a0[co] = 0.f; a1[co] = 0.f; }

#pragma unroll 4
    for (int ci = 0; ci < 16; ci++) {
        float xv[6];
#pragma unroll
        for (int j = 0; j < 6; j++) xv[j] = xs[ci][2 * lt + j];
#pragma unroll
        for (int co = 0; co < 32; co++) {
#pragma unroll
            for (int k = 0; k < 5; k++) {
                float wv = ws[(co * 16 + ci) * 5 + k];
                a0[co] += wv * xv[k];
                a1[co] += wv * xv[k + 1];
            }
        }
    }

    float* ob = g_o2 + (size_t)b * 32 * RT_ + (t0 + lt);
#pragma unroll
    for (int co = 0; co < 32; co++)
        ob[(size_t)co * RT_] = fmaxf(fmaxf(a0[co], a1[co]) + bs[co], 0.f);
}

// ---------------------------------------------------------------------------
// GCN1: z = Anorm * x (3-tap chain stencil in input space), h1 = relu(z@W1 + b1)
// Block = one (batch, 128-row p-chunk) x 128 cols; 256 threads, 8x8 reg tiles.
// grid 4096, 256 threads
// ---------------------------------------------------------------------------
__global__ __launch_bounds__(256) void gcn1_kernel(const float* __restrict__ W,
                                                   const float* __restrict__ bias) {
    __shared__ float zs[32][128];
    __shared__ float wsm[32][128];
    const int bx = blockIdx.x;
    const int b = bx >> 2, p0 = (bx & 3) << 7;
    const int tid = threadIdx.x;

    for (int e = tid; e < 4096; e += 256) wsm[e >> 7][e & 127] = W[e];

    const float* gb = g_o2 + (size_t)b * 32 * RT_;
    for (int e = tid; e < 4096; e += 256) {
        int f = e >> 7, p = e & 127;
        int pp = p0 + p;
        float di = (pp == 0 || pp == RT_ - 1) ? RS2 : RS3;
        float z = di * di * gb[f * RT_ + pp];
        if (pp > 0) {
            float dp = (pp == 1) ? RS2 : RS3;
            z += di * dp * gb[f * RT_ + pp - 1];
        }
        if (pp < RT_ - 1) {
            float dn = (pp == RT_ - 2) ? RS2 : RS3;
            z += di * dn * gb[f * RT_ + pp + 1];
        }
        zs[f][p] = z;
    }
    __syncthreads();

    const int ty = tid >> 4, tx = tid & 15;
    unsigned long long acc[8][4];
#pragma unroll
    for (int i = 0; i < 8; i++)
#pragma unroll
        for (int c = 0; c < 4; c++) acc[i][c] = 0ull;

#pragma unroll 4
    for (int kk = 0; kk < 32; kk++) {
        unsigned long long ad[8], bw[4];
#pragma unroll
        for (int i = 0; i < 8; i++) ad[i] = dup2(zs[kk][ty * 8 + i]);
#pragma unroll
        for (int c = 0; c < 4; c++)
            bw[c] = *(const unsigned long long*)&wsm[kk][tx * 8 + 2 * c];
#pragma unroll
        for (int i = 0; i < 8; i++)
#pragma unroll
            for (int c = 0; c < 4; c++) FFMA2(acc[i][c], ad[i], bw[c]);
    }

    float bv[8];
#pragma unroll
    for (int j = 0; j < 8; j++) bv[j] = bias[tx * 8 + j];

    const size_t nb = ((size_t)b * RT_ + p0 + ty * 8) * HID_ + tx * 8;
#pragma unroll
    for (int i = 0; i < 8; i++) {
#pragma unroll
        for (int c = 0; c < 4; c++) {
            float lo = __uint_as_float((unsigned)(acc[i][c] & 0xffffffffull));
            float hi = __uint_as_float((unsigned)(acc[i][c] >> 32));
            float2 v;
            v.x = fmaxf(lo + bv[2 * c], 0.f);
            v.y = fmaxf(hi + bv[2 * c + 1], 0.f);
            *(float2*)&g_h1[nb + (size_t)i * HID_ + 2 * c] = v;
        }
    }
}

// ---------------------------------------------------------------------------
// GCN2: z2 = Anorm * h1 (stencil on h1 rows during load), acc = z2 @ W2,
// epilogue: relu(acc+b2), sum over the 128 rows of the block -> g_bsum slot.
// grid 4096, 256 threads
// ---------------------------------------------------------------------------
__global__ __launch_bounds__(256) void gcn2_kernel(const float* __restrict__ W,
                                                   const float* __restrict__ bias) {
    __shared__ float zs[32][133];   // stride 133: conflict-free transposed stores
    __shared__ float wsm[32][128];
    __shared__ float red[16][128];
    const int bx = blockIdx.x;
    const int b = bx >> 2, p0 = (bx & 3) << 7;
    const int tid = threadIdx.x;
    const int ty = tid >> 4, tx = tid & 15;
    const int lk = tid & 31, lp0 = tid >> 5;

    unsigned long long acc[8][4];
#pragma unroll
    for (int i = 0; i < 8; i++)
#pragma unroll
        for (int c = 0; c < 4; c++) acc[i][c] = 0ull;

    for (int ch = 0; ch < 4; ch++) {
        const int k0 = ch * 32;
        if (ch) __syncthreads();
        for (int e = tid; e < 4096; e += 256)
            wsm[e >> 7][e & 127] = W[(size_t)(k0 + (e >> 7)) * HID_ + (e & 127)];
#pragma unroll 4
        for (int r = 0; r < 16; r++) {
            int p = lp0 + r * 8;
            int pp = p0 + p;
            size_t node = (size_t)b * RT_ + pp;
            float di = (pp == 0 || pp == RT_ - 1) ? RS2 : RS3;
            float z = di * di * g_h1[node * HID_ + k0 + lk];
            if (pp > 0) {
                float dp = (pp == 1) ? RS2 : RS3;
                z += di * dp * g_h1[(node - 1) * HID_ + k0 + lk];
            }
            if (pp < RT_ - 1) {
                float dn = (pp == RT_ - 2) ? RS2 : RS3;
                z += di * dn * g_h1[(node + 1) * HID_ + k0 + lk];
            }
            zs[lk][p] = z;
        }
        __syncthreads();

#pragma unroll 4
        for (int kk = 0; kk < 32; kk++) {
            unsigned long long ad[8], bw[4];
#pragma unroll
            for (int i = 0; i < 8; i++) ad[i] = dup2(zs[kk][ty * 8 + i]);
#pragma unroll
            for (int c = 0; c < 4; c++)
                bw[c] = *(const unsigned long long*)&wsm[kk][tx * 8 + 2 * c];
#pragma unroll
            for (int i = 0; i < 8; i++)
#pragma unroll
                for (int c = 0; c < 4; c++) FFMA2(acc[i][c], ad[i], bw[c]);
        }
    }

    // epilogue: relu(acc + b2) then sum over this thread's 8 rows
    float bv[8];
#pragma unroll
    for (int j = 0; j < 8; j++) bv[j] = bias[tx * 8 + j];

    float csum[8];
#pragma unroll
    for (int j = 0; j < 8; j++) csum[j] = 0.f;
#pragma unroll
    for (int i = 0; i < 8; i++) {
#pragma unroll
        for (int c = 0; c < 4; c++) {
            float lo = __uint_as_float((unsigned)(acc[i][c] & 0xffffffffull));
            float hi = __uint_as_float((unsigned)(acc[i][c] >> 32));
            csum[2 * c]     += fmaxf(lo + bv[2 * c], 0.f);
            csum[2 * c + 1] += fmaxf(hi + bv[2 * c + 1], 0.f);
        }
    }
    __syncthreads();   // done reading zs/wsm; red is separate but keep ordering clean
#pragma unroll
    for (int j = 0; j < 8; j++) red[ty][tx * 8 + j] = csum[j];
    __syncthreads();

    if (tid < 128) {
        float s = 0.f;
#pragma unroll
        for (int g = 0; g < 16; g++) s += red[g][tid];
        g_bsum[((size_t)b * 4 + (bx & 3)) * HID_ + tid] = s;  // deterministic slot
    }
}

// ---------------------------------------------------------------------------
// mean over RT (sum of 4 chunk partials / 512) then fc: out[b,o]
// grid 1024, 64 threads
// ---------------------------------------------------------------------------
__global__ void fc_kernel(const float* __restrict__ fw,
                          const float* __restrict__ fb,
                          float* __restrict__ out) {
    __shared__ float s[128];
    const int b = blockIdx.x, o = threadIdx.x;
    {
        float v0 = 0.f, v1 = 0.f;
#pragma unroll
        for (int c = 0; c < 4; c++) {
            v0 += g_bsum[((size_t)b * 4 + c) * HID_ + o];
            v1 += g_bsum[((size_t)b * 4 + c) * HID_ + o + 64];
        }
        s[o] = v0;
        s[o + 64] = v1;
    }
    __syncthreads();
    float a = 0.f;
#pragma unroll
    for (int k = 0; k < 128; k++) a += s[k] * fw[k * 64 + o];
    out[b * 64 + o] = a * (1.f / 512.f) + fb[o];
}

// ---------------------------------------------------------------------------
extern "C" void kernel_launch(void* const* d_in, const int* in_sizes, int n_in,
                              void* d_out, int out_size) {
    const float* x   = (const float*)d_in[0];
    const float* c1w = (const float*)d_in[1];
    const float* c1b = (const float*)d_in[2];
    const float* c2w = (const float*)d_in[3];
    const float* c2b = (const float*)d_in[4];
    const float* g1w = (const float*)d_in[5];
    const float* g1b = (const float*)d_in[6];
    const float* g2w = (const float*)d_in[7];
    const float* g2b = (const float*)d_in[8];
    const float* fw  = (const float*)d_in[9];
    const float* fb  = (const float*)d_in[10];
    float* out = (float*)d_out;

    conv1_kernel<<<dim3(B_, 8), 128>>>(x, c1w, c1b);
    conv2_kernel<<<dim3(B_, 4), 128>>>(c2w, c2b);
    gcn1_kernel<<<B_ * 4, 256>>>(g1w, g1b);
    gcn2_kernel<<<B_ * 4, 256>>>(g2w, g2b);
    fc_kernel<<<B_, 64>>>(fw, fb, out);
}

// round 2
// speedup vs baseline: 1.2951x; 1.2951x over previous
#include <cuda_runtime.h>
#include <cuda_bf16.h>
#include <cstdint>

// ---------------------------------------------------------------------------
// TemporalGCN: conv1+relu+pool -> conv2+relu+pool -> GCN1 -> GCN2 -> mean -> fc
// B=1024, C_IN=9, T=2048, RT=512, HID=128, OUT=64
//
// R2: GCN2 moved to tf32 mma.sync tensor cores (m16n8k8), h1 stored bf16.
// GCN aggregation folded into GEMM A-operand (chain stencil), GCN2 epilogue
// does relu + per-batch column sums (h2 never hits DRAM).
// ---------------------------------------------------------------------------

#define B_      1024
#define T_      2048
#define T1_     1024
#define RT_     512
#define HID_    128

static __device__ float          g_o1[(size_t)B_ * 16 * T1_];   // conv1 out
static __device__ float          g_o2[(size_t)B_ * 32 * RT_];   // conv2 out
static __device__ __nv_bfloat16  g_h1[(size_t)B_ * RT_ * HID_]; // gcn1 out (bf16)
static __device__ float          g_bsum[(size_t)B_ * 4 * HID_]; // per-(b,chunk) colsums

__device__ __forceinline__ unsigned long long dup2(float a) {
    unsigned ai = __float_as_uint(a);
    unsigned long long r;
    asm("mov.b64 %0, {%1, %1};" : "=l"(r) : "r"(ai));
    return r;
}
#define FFMA2(d, a, b) asm("fma.rn.f32x2 %0, %1, %2, %0;" : "+l"(d) : "l"(a), "l"(b))

__device__ __forceinline__ unsigned tf32r(float x) {
    unsigned r;
    asm("cvt.rna.tf32.f32 %0, %1;" : "=r"(r) : "f"(x));
    return r;
}

__device__ __forceinline__ void mma_tf32(float c[4],
                                         unsigned a0, unsigned a1, unsigned a2, unsigned a3,
                                         unsigned b0, unsigned b1) {
    asm volatile(
        "mma.sync.aligned.m16n8k8.row.col.f32.tf32.tf32.f32 "
        "{%0,%1,%2,%3},{%4,%5,%6,%7},{%8,%9},{%0,%1,%2,%3};"
        : "+f"(c[0]), "+f"(c[1]), "+f"(c[2]), "+f"(c[3])
        : "r"(a0), "r"(a1), "r"(a2), "r"(a3), "r"(b0), "r"(b1));
}

#define RS2 0.70710678118654752f   // 2^-1/2
#define RS3 0.57735026918962576f   // 3^-1/2

// ---------------------------------------------------------------------------
// conv1 + relu + maxpool2 : x[B,9,2048] -> g_o1[B,16,1024]
// ---------------------------------------------------------------------------
__global__ void conv1_kernel(const float* __restrict__ x,
                             const float* __restrict__ w,
                             const float* __restrict__ bias) {
    __shared__ float xs[9][260];
    __shared__ float ws[16 * 9 * 5];
    __shared__ float bs[16];
    const int b = blockIdx.x, t0 = blockIdx.y * 128, tid = threadIdx.x;

    for (int e = tid; e < 720; e += 128) ws[e] = w[e];
    if (tid < 16) bs[tid] = bias[tid];

    const float* xb = x + (size_t)b * 9 * T_;
    const int base = 2 * t0 - 2;
    for (int e = tid; e < 9 * 260; e += 128) {
        int ci = e / 260, j = e % 260;
        int t = base + j;
        xs[ci][j] = (t >= 0 && t < T_) ? xb[ci * T_ + t] : 0.f;
    }
    __syncthreads();

    const int lt = tid;
    float xv[9][6];
#pragma unroll
    for (int ci = 0; ci < 9; ci++)
#pragma unroll
        for (int j = 0; j < 6; j++) xv[ci][j] = xs[ci][2 * lt + j];

    float* ob = g_o1 + (size_t)b * 16 * T1_ + (t0 + lt);
#pragma unroll
    for (int co = 0; co < 16; co++) {
        float a0 = 0.f, a1 = 0.f;
#pragma unroll
        for (int ci = 0; ci < 9; ci++)
#pragma unroll
            for (int k = 0; k < 5; k++) {
                float wv = ws[(co * 9 + ci) * 5 + k];
                a0 += wv * xv[ci][k];
                a1 += wv * xv[ci][k + 1];
            }
        ob[(size_t)co * T1_] = fmaxf(fmaxf(a0, a1) + bs[co], 0.f);
    }
}

// ---------------------------------------------------------------------------
// conv2 + relu + maxpool2 : g_o1[B,16,1024] -> g_o2[B,32,512]
// ---------------------------------------------------------------------------
__global__ void conv2_kernel(const float* __restrict__ w,
                             const float* __restrict__ bias) {
    __shared__ float xs[16][260];
    __shared__ float ws[32 * 16 * 5];
    __shared__ float bs[32];
    const int b = blockIdx.x, t0 = blockIdx.y * 128, tid = threadIdx.x;

    for (int e = tid; e < 2560; e += 128) ws[e] = w[e];
    if (tid < 32) bs[tid] = bias[tid];

    const float* xb = g_o1 + (size_t)b * 16 * T1_;
    const int base = 2 * t0 - 2;
    for (int e = tid; e < 16 * 260; e += 128) {
        int ci = e / 260, j = e % 260;
        int t = base + j;
        xs[ci][j] = (t >= 0 && t < T1_) ? xb[ci * T1_ + t] : 0.f;
    }
    __syncthreads();

    const int lt = tid;
    float a0[32], a1[32];
#pragma unroll
    for (int co = 0; co < 32; co++) { a0[co] = 0.f; a1[co] = 0.f; }

#pragma unroll 4
    for (int ci = 0; ci < 16; ci++) {
        float xv[6];
#pragma unroll
        for (int j = 0; j < 6; j++) xv[j] = xs[ci][2 * lt + j];
#pragma unroll
        for (int co = 0; co < 32; co++) {
#pragma unroll
            for (int k = 0; k < 5; k++) {
                float wv = ws[(co * 16 + ci) * 5 + k];
                a0[co] += wv * xv[k];
                a1[co] += wv * xv[k + 1];
            }
        }
    }

    float* ob = g_o2 + (size_t)b * 32 * RT_ + (t0 + lt);
#pragma unroll
    for (int co = 0; co < 32; co++)
        ob[(size_t)co * RT_] = fmaxf(fmaxf(a0[co], a1[co]) + bs[co], 0.f);
}

// ---------------------------------------------------------------------------
// GCN1: z = Anorm*x (3-tap chain stencil), h1 = relu(z@W1 + b1) -> bf16
// FFMA2 path (K=32, mostly memory-bound). grid 4096, 256 threads.
// ---------------------------------------------------------------------------
__global__ __launch_bounds__(256) void gcn1_kernel(const float* __restrict__ W,
                                                   const float* __restrict__ bias) {
    __shared__ float zs[32][128];
    __shared__ float wsm[32][128];
    const int bx = blockIdx.x;
    const int b = bx >> 2, p0 = (bx & 3) << 7;
    const int tid = threadIdx.x;

    for (int e = tid; e < 4096; e += 256) wsm[e >> 7][e & 127] = W[e];

    const float* gb = g_o2 + (size_t)b * 32 * RT_;
    for (int e = tid; e < 4096; e += 256) {
        int f = e >> 7, p = e & 127;
        int pp = p0 + p;
        float di = (pp == 0 || pp == RT_ - 1) ? RS2 : RS3;
        float z = di * di * gb[f * RT_ + pp];
        if (pp > 0) {
            float dp = (pp == 1) ? RS2 : RS3;
            z += di * dp * gb[f * RT_ + pp - 1];
        }
        if (pp < RT_ - 1) {
            float dn = (pp == RT_ - 2) ? RS2 : RS3;
            z += di * dn * gb[f * RT_ + pp + 1];
        }
        zs[f][p] = z;
    }
    __syncthreads();

    const int ty = tid >> 4, tx = tid & 15;
    unsigned long long acc[8][4];
#pragma unroll
    for (int i = 0; i < 8; i++)
#pragma unroll
        for (int c = 0; c < 4; c++) acc[i][c] = 0ull;

#pragma unroll 4
    for (int kk = 0; kk < 32; kk++) {
        unsigned long long ad[8], bw[4];
#pragma unroll
        for (int i = 0; i < 8; i++) ad[i] = dup2(zs[kk][ty * 8 + i]);
#pragma unroll
        for (int c = 0; c < 4; c++)
            bw[c] = *(const unsigned long long*)&wsm[kk][tx * 8 + 2 * c];
#pragma unroll
        for (int i = 0; i < 8; i++)
#pragma unroll
            for (int c = 0; c < 4; c++) FFMA2(acc[i][c], ad[i], bw[c]);
    }

    float bv[8];
#pragma unroll
    for (int j = 0; j < 8; j++) bv[j] = bias[tx * 8 + j];

    const size_t nb = ((size_t)b * RT_ + p0 + ty * 8) * HID_ + tx * 8;
#pragma unroll
    for (int i = 0; i < 8; i++) {
#pragma unroll
        for (int c = 0; c < 4; c++) {
            float lo = __uint_as_float((unsigned)(acc[i][c] & 0xffffffffull));
            float hi = __uint_as_float((unsigned)(acc[i][c] >> 32));
            float vx = fmaxf(lo + bv[2 * c], 0.f);
            float vy = fmaxf(hi + bv[2 * c + 1], 0.f);
            *(__nv_bfloat162*)&g_h1[nb + (size_t)i * HID_ + 2 * c] =
                __floats2bfloat162_rn(vx, vy);
        }
    }
}

// ---------------------------------------------------------------------------
// GCN2 (tf32 tensor cores): z2 = Anorm*h1 (stencil on bf16 h1 during load),
// acc = z2 @ W2 via mma.sync.m16n8k8.tf32, epilogue relu+bias+column sums.
// Block: 128 rows x 128 cols, K=128 in 4 chunks of 32. 256 threads = 8 warps
// (4 m-warps x 2 n-warps). grid 4096.
// smem fragments are pre-paired float2 with strides chosen so every LDS.64
// hits the 2-phase floor (bank = 2r + 8k pattern).
// ---------------------------------------------------------------------------
__global__ __launch_bounds__(256) void gcn2_kernel(const float* __restrict__ W,
                                                   const float* __restrict__ bias) {
    __shared__ float2 zp[32][68];     // [k_local][mtile*8 + r], {z[p], z[p+8]}
    __shared__ float2 wp[4][4][132];  // [kstep][klo][n],       {W[k][n], W[k+4][n]}
    __shared__ float  red[4][128];
    __shared__ float  bsm[128];

    const int bx = blockIdx.x;
    const int b = bx >> 2, p0 = (bx & 3) << 7;
    const int tid = threadIdx.x;
    const int lane = tid & 31;
    const int warp = tid >> 5;
    const int wm = warp >> 1;          // m-warp 0..3 (rows wm*32..wm*32+31)
    const int wn = warp & 1;           // n-warp 0..1 (cols wn*64..wn*64+63)
    const int l4 = lane & 3, l8 = lane >> 2;

    if (tid < 128) bsm[tid] = bias[tid];

    float acc[2][8][4];
#pragma unroll
    for (int i = 0; i < 2; i++)
#pragma unroll
        for (int j = 0; j < 8; j++)
#pragma unroll
            for (int c = 0; c < 4; c++) acc[i][j][c] = 0.f;

    // producer indexing for zp: each thread: col-pair lk2, rows rg + r*16
    const int lk2 = tid & 15;          // covers cols 2*lk2, 2*lk2+1 of the chunk
    const int rg  = tid >> 4;          // row group 0..15

    for (int ch = 0; ch < 4; ch++) {
        const int k0 = ch * 32;
        __syncthreads();               // protect previous chunk's reads

        // --- fill wp (W chunk, tf32-rounded, paired k/k+4) ---
        for (int e = tid; e < 4096; e += 256) {
            int k = e >> 7, n = e & 127;
            int rem = k & 7;
            float wv = W[(size_t)(k0 + k) * HID_ + n];
            ((float*)&wp[k >> 3][rem & 3][n])[rem >> 2] = __uint_as_float(tf32r(wv));
        }

        // --- fill zp (stencil over bf16 h1, tf32-rounded, paired p/p+8) ---
#pragma unroll
        for (int r = 0; r < 8; r++) {
            int p = rg + r * 16;
            int pp = p0 + p;
            size_t node = (size_t)b * RT_ + pp;
            float di = (pp == 0 || pp == RT_ - 1) ? RS2 : RS3;
            const __nv_bfloat162* hc =
                (const __nv_bfloat162*)&g_h1[node * HID_ + k0 + 2 * lk2];
            float2 c = __bfloat1622float2(*hc);
            float2 z;
            z.x = di * di * c.x;
            z.y = di * di * c.y;
            if (pp > 0) {
                float dp = (pp == 1) ? RS2 : RS3;
                float2 v = __bfloat1622float2(
                    *(const __nv_bfloat162*)&g_h1[(node - 1) * HID_ + k0 + 2 * lk2]);
                z.x += di * dp * v.x;
                z.y += di * dp * v.y;
            }
            if (pp < RT_ - 1) {
                float dn = (pp == RT_ - 2) ? RS2 : RS3;
                float2 v = __bfloat1622float2(
                    *(const __nv_bfloat162*)&g_h1[(node + 1) * HID_ + k0 + 2 * lk2]);
                z.x += di * dn * v.x;
                z.y += di * dn * v.y;
            }
            int mt = p >> 4, r8 = p & 7, hi = (p >> 3) & 1;
            ((float*)&zp[2 * lk2][mt * 8 + r8])[hi]     = __uint_as_float(tf32r(z.x));
            ((float*)&zp[2 * lk2 + 1][mt * 8 + r8])[hi] = __uint_as_float(tf32r(z.y));
        }
        __syncthreads();

        // --- mma main loop: 4 k-steps of 8 ---
#pragma unroll
        for (int ks = 0; ks < 4; ks++) {
            unsigned a[2][4];
#pragma unroll
            for (int i = 0; i < 2; i++) {
                int mt8 = (wm * 2 + i) * 8;
                float2 a01 = zp[ks * 8 + l4][mt8 + l8];
                float2 a23 = zp[ks * 8 + 4 + l4][mt8 + l8];
                a[i][0] = __float_as_uint(a01.x);
                a[i][1] = __float_as_uint(a01.y);
                a[i][2] = __float_as_uint(a23.x);
                a[i][3] = __float_as_uint(a23.y);
            }
#pragma unroll
            for (int j = 0; j < 8; j++) {
                float2 b01 = wp[ks][l4][wn * 64 + j * 8 + l8];
                unsigned bb0 = __float_as_uint(b01.x);
                unsigned bb1 = __float_as_uint(b01.y);
#pragma unroll
                for (int i = 0; i < 2; i++)
                    mma_tf32(acc[i][j], a[i][0], a[i][1], a[i][2], a[i][3], bb0, bb1);
            }
        }
    }

    // --- epilogue: relu(acc + bias), column partial sums, warp bfly reduce ---
    float s[8][2];
#pragma unroll
    for (int j = 0; j < 8; j++) {
        int colb = wn * 64 + j * 8 + 2 * l4;
        float b0v = bsm[colb], b1v = bsm[colb + 1];
        float s0 = 0.f, s1 = 0.f;
#pragma unroll
        for (int i = 0; i < 2; i++) {
            s0 += fmaxf(acc[i][j][0] + b0v, 0.f) + fmaxf(acc[i][j][2] + b0v, 0.f);
            s1 += fmaxf(acc[i][j][1] + b1v, 0.f) + fmaxf(acc[i][j][3] + b1v, 0.f);
        }
        s[j][0] = s0;
        s[j][1] = s1;
    }
#pragma unroll
    for (int j = 0; j < 8; j++)
#pragma unroll
        for (int lo = 0; lo < 2; lo++) {
            float v = s[j][lo];
            v += __shfl_xor_sync(0xffffffffu, v, 4);
            v += __shfl_xor_sync(0xffffffffu, v, 8);
            v += __shfl_xor_sync(0xffffffffu, v, 16);
            s[j][lo] = v;
        }
    if (lane < 4) {
#pragma unroll
        for (int j = 0; j < 8; j++) {
#pragma unroll
            for (int lo = 0; lo < 2; lo++)
                red[wm][wn * 64 + j * 8 + 2 * lane + lo] = s[j][lo];
        }
    }
    __syncthreads();

    if (tid < 128) {
        float t = red[0][tid] + red[1][tid] + red[2][tid] + red[3][tid];
        g_bsum[((size_t)b * 4 + (bx & 3)) * HID_ + tid] = t;
    }
}

// ---------------------------------------------------------------------------
// mean over RT (sum of 4 chunk partials / 512) then fc
// ---------------------------------------------------------------------------
__global__ void fc_kernel(const float* __restrict__ fw,
                          const float* __restrict__ fb,
                          float* __restrict__ out) {
    __shared__ float s[128];
    const int b = blockIdx.x, o = threadIdx.x;
    {
        float v0 = 0.f, v1 = 0.f;
#pragma unroll
        for (int c = 0; c < 4; c++) {
            v0 += g_bsum[((size_t)b * 4 + c) * HID_ + o];
            v1 += g_bsum[((size_t)b * 4 + c) * HID_ + o + 64];
        }
        s[o] = v0;
        s[o + 64] = v1;
    }
    __syncthreads();
    float a = 0.f;
#pragma unroll
    for (int k = 0; k < 128; k++) a += s[k] * fw[k * 64 + o];
    out[b * 64 + o] = a * (1.f / 512.f) + fb[o];
}

// ---------------------------------------------------------------------------
extern "C" void kernel_launch(void* const* d_in, const int* in_sizes, int n_in,
                              void* d_out, int out_size) {
    const float* x   = (const float*)d_in[0];
    const float* c1w = (const float*)d_in[1];
    const float* c1b = (const float*)d_in[2];
    const float* c2w = (const float*)d_in[3];
    const float* c2b = (const float*)d_in[4];
    const float* g1w = (const float*)d_in[5];
    const float* g1b = (const float*)d_in[6];
    const float* g2w = (const float*)d_in[7];
    const float* g2b = (const float*)d_in[8];
    const float* fw  = (const float*)d_in[9];
    const float* fb  = (const float*)d_in[10];
    float* out = (float*)d_out;

    conv1_kernel<<<dim3(B_, 8), 128>>>(x, c1w, c1b);
    conv2_kernel<<<dim3(B_, 4), 128>>>(c2w, c2b);
    gcn1_kernel<<<B_ * 4, 256>>>(g1w, g1b);
    gcn2_kernel<<<B_ * 4, 256>>>(g2w, g2b);
    fc_kernel<<<B_, 64>>>(fw, fb, out);
}

// round 8
// speedup vs baseline: 1.8706x; 1.4444x over previous
#include <cuda_runtime.h>
#include <cuda_bf16.h>
#include <cstdint>

// ---------------------------------------------------------------------------
// TemporalGCN: conv1+relu+pool -> conv2+relu+pool -> GCN1 -> GCN2 -> mean -> fc
// B=1024, C_IN=9, T=2048, RT=512, HID=128, OUT=64
//
// R7 (resubmit after timeout): bf16 mma.m16n8k16 GEMMs with SPLIT WEIGHTS
// (hi+lo bf16, 2 mma passes). Weight quantization error is systematic across
// the node-mean and must be tiny; activation (A-operand) bf16 error is
// node-dependent and averages out. Chain-stencil aggregation folded into A;
// GCN2 epilogue does relu + column sums (h2 never hits DRAM). Convs exact
// fp32 with f32x2 packing.
// ---------------------------------------------------------------------------

#define B_      1024
#define T_      2048
#define T1_     1024
#define RT_     512
#define HID_    128

static __device__ float          g_o1[(size_t)B_ * 16 * T1_];   // conv1 out
static __device__ float          g_o2[(size_t)B_ * 32 * RT_];   // conv2 out
static __device__ __nv_bfloat16  g_h1[(size_t)B_ * RT_ * HID_]; // gcn1 out (bf16)
static __device__ float          g_bsum[(size_t)B_ * 4 * HID_]; // per-(b,chunk) colsums

__device__ __forceinline__ unsigned long long dup2(float a) {
    unsigned ai = __float_as_uint(a);
    unsigned long long r;
    asm("mov.b64 %0, {%1, %1};" : "=l"(r) : "r"(ai));
    return r;
}
__device__ __forceinline__ unsigned long long packf2(float lo, float hi) {
    unsigned long long r;
    asm("mov.b64 %0, {%1, %2};" : "=l"(r) : "f"(lo), "f"(hi));
    return r;
}
#define FFMA2(d, a, b) asm("fma.rn.f32x2 %0, %1, %2, %0;" : "+l"(d) : "l"(a), "l"(b))

__device__ __forceinline__ unsigned pk(float lo, float hi) {
    __nv_bfloat162 t = __floats2bfloat162_rn(lo, hi);
    return *(unsigned*)&t;
}
__device__ __forceinline__ float2 upk(unsigned u) {
    return __bfloat1622float2(*(__nv_bfloat162*)&u);
}
// split pair (a,b) into hi bf16x2 word and lo (residual) bf16x2 word
__device__ __forceinline__ void pksplit(float a, float b, unsigned& hi, unsigned& lo) {
    __nv_bfloat16 ah = __float2bfloat16(a);
    __nv_bfloat16 bh = __float2bfloat16(b);
    __nv_bfloat162 h2;
    h2.x = ah; h2.y = bh;
    hi = *(unsigned*)&h2;
    lo = pk(a - __bfloat162float(ah), b - __bfloat162float(bh));
}

__device__ __forceinline__ void mma_bf16(float c[4],
                                         unsigned a0, unsigned a1, unsigned a2, unsigned a3,
                                         unsigned b0, unsigned b1) {
    asm volatile(
        "mma.sync.aligned.m16n8k16.row.col.f32.bf16.bf16.f32 "
        "{%0,%1,%2,%3},{%4,%5,%6,%7},{%8,%9},{%0,%1,%2,%3};"
        : "+f"(c[0]), "+f"(c[1]), "+f"(c[2]), "+f"(c[3])
        : "r"(a0), "r"(a1), "r"(a2), "r"(a3), "r"(b0), "r"(b1));
}

#define RS2 0.70710678118654752f   // 2^-1/2
#define RS3 0.57735026918962576f   // 3^-1/2

// ---------------------------------------------------------------------------
// conv1 + relu + maxpool2 : x[B,9,2048] -> g_o1[B,16,1024]
// ---------------------------------------------------------------------------
__global__ void conv1_kernel(const float* __restrict__ x,
                             const float* __restrict__ w,
                             const float* __restrict__ bias) {
    __shared__ float xs[9][260];
    __shared__ unsigned long long ws2[720];
    __shared__ float bs[16];
    const int b = blockIdx.x, t0 = blockIdx.y * 128, tid = threadIdx.x;

    for (int e = tid; e < 720; e += 128) ws2[e] = dup2(w[e]);
    if (tid < 16) bs[tid] = bias[tid];

    const float* xb = x + (size_t)b * 9 * T_;
    const int base = 2 * t0 - 2;
    for (int e = tid; e < 9 * 260; e += 128) {
        int ci = e / 260, j = e % 260;
        int t = base + j;
        xs[ci][j] = (t >= 0 && t < T_) ? xb[ci * T_ + t] : 0.f;
    }
    __syncthreads();

    const int lt = tid;
    unsigned long long xp[9][5];
#pragma unroll
    for (int ci = 0; ci < 9; ci++) {
        float xv[6];
#pragma unroll
        for (int j = 0; j < 6; j++) xv[j] = xs[ci][2 * lt + j];
#pragma unroll
        for (int k = 0; k < 5; k++) xp[ci][k] = packf2(xv[k], xv[k + 1]);
    }

    float* ob = g_o1 + (size_t)b * 16 * T1_ + (t0 + lt);
#pragma unroll
    for (int co = 0; co < 16; co++) {
        unsigned long long a = 0ull;
#pragma unroll
        for (int ci = 0; ci < 9; ci++)
#pragma unroll
            for (int k = 0; k < 5; k++)
                FFMA2(a, ws2[(co * 9 + ci) * 5 + k], xp[ci][k]);
        float lo = __uint_as_float((unsigned)(a & 0xffffffffull));
        float hi = __uint_as_float((unsigned)(a >> 32));
        ob[(size_t)co * T1_] = fmaxf(fmaxf(lo, hi) + bs[co], 0.f);
    }
}

// ---------------------------------------------------------------------------
// conv2 + relu + maxpool2 : g_o1[B,16,1024] -> g_o2[B,32,512]
// ---------------------------------------------------------------------------
__global__ void conv2_kernel(const float* __restrict__ w,
                             const float* __restrict__ bias) {
    __shared__ float xs[16][260];
    __shared__ unsigned long long ws2[2560];
    __shared__ float bs[32];
    const int b = blockIdx.x, t0 = blockIdx.y * 128, tid = threadIdx.x;

    for (int e = tid; e < 2560; e += 128) ws2[e] = dup2(w[e]);
    if (tid < 32) bs[tid] = bias[tid];

    const float* xb = g_o1 + (size_t)b * 16 * T1_;
    const int base = 2 * t0 - 2;
    for (int e = tid; e < 16 * 260; e += 128) {
        int ci = e / 260, j = e % 260;
        int t = base + j;
        xs[ci][j] = (t >= 0 && t < T1_) ? xb[ci * T1_ + t] : 0.f;
    }
    __syncthreads();

    const int lt = tid;
    unsigned long long a[32];
#pragma unroll
    for (int co = 0; co < 32; co++) a[co] = 0ull;

#pragma unroll 2
    for (int ci = 0; ci < 16; ci++) {
        float xv[6];
#pragma unroll
        for (int j = 0; j < 6; j++) xv[j] = xs[ci][2 * lt + j];
        unsigned long long xp[5];
#pragma unroll
        for (int k = 0; k < 5; k++) xp[k] = packf2(xv[k], xv[k + 1]);
#pragma unroll
        for (int co = 0; co < 32; co++)
#pragma unroll
            for (int k = 0; k < 5; k++)
                FFMA2(a[co], ws2[(co * 16 + ci) * 5 + k], xp[k]);
    }

    float* ob = g_o2 + (size_t)b * 32 * RT_ + (t0 + lt);
#pragma unroll
    for (int co = 0; co < 32; co++) {
        float lo = __uint_as_float((unsigned)(a[co] & 0xffffffffull));
        float hi = __uint_as_float((unsigned)(a[co] >> 32));
        ob[(size_t)co * RT_] = fmaxf(fmaxf(lo, hi) + bs[co], 0.f);
    }
}

// ---------------------------------------------------------------------------
// GCN1 (bf16 mma, split W): z = Anorm*o2 (stencil), h1 = relu(z@W1+b1) -> bf16
// 128 rows x 128 cols, K=32 (2 ksteps). 8 warps = 4m x 2n. grid 4096.
// W1 split hi/lo bf16; A single bf16 (node-dependent error averages out).
// ---------------------------------------------------------------------------
__global__ __launch_bounds__(256) void gcn1_kernel(const float* __restrict__ W,
                                                   const float* __restrict__ bias) {
    __shared__ uint2 za[16][68];
    __shared__ uint2 wph[8][132];
    __shared__ uint2 wpl[8][132];
    __shared__ float bsm[128];
    const int bx = blockIdx.x, b = bx >> 2, p0 = (bx & 3) << 7;
    const int tid = threadIdx.x, lane = tid & 31, warp = tid >> 5;
    const int wm = warp >> 1, wn = warp & 1, l4 = lane & 3, l8 = lane >> 2;

    if (tid < 128) bsm[tid] = bias[tid];

    // fill wph/wpl from W1 [32][128]
    {
        int n = tid & 127, fb = (tid >> 7) * 4;
#pragma unroll
        for (int i = 0; i < 4; i++) {
            int f = fb + i, ks = f >> 2, klo = f & 3;
            int ka = 2 * (ks * 8 + klo);
            unsigned hx, lx, hy, ly;
            pksplit(W[ka * HID_ + n], W[(ka + 1) * HID_ + n], hx, lx);
            pksplit(W[(ka + 8) * HID_ + n], W[(ka + 9) * HID_ + n], hy, ly);
            uint2 vh; vh.x = hx; vh.y = hy;
            uint2 vl; vl.x = lx; vl.y = ly;
            wph[f][n] = vh;
            wpl[f][n] = vl;
        }
    }
    // fill za: stencil over g_o2 [b][32 f][512 p]
    {
        const float* gb = g_o2 + (size_t)b * 32 * RT_;
        const int kp = 2 * warp + (lane >> 4);
        const int rl = lane & 15;
#pragma unroll
        for (int i = 0; i < 4; i++) {
            int ridx = rl + 16 * i;
            int r0 = ((ridx >> 3) << 4) + (ridx & 7);
            uint2 v;
#pragma unroll
            for (int h = 0; h < 2; h++) {
                int pp = p0 + r0 + h * 8;
                float di = (pp == 0 || pp == RT_ - 1) ? RS2 : RS3;
                const float* c0 = gb + (2 * kp) * RT_ + pp;
                const float* c1 = gb + (2 * kp + 1) * RT_ + pp;
                float z0 = di * di * c0[0];
                float z1 = di * di * c1[0];
                if (pp > 0) {
                    float dp = (pp == 1) ? RS2 : RS3;
                    z0 += di * dp * c0[-1];
                    z1 += di * dp * c1[-1];
                }
                if (pp < RT_ - 1) {
                    float dn = (pp == RT_ - 2) ? RS2 : RS3;
                    z0 += di * dn * c0[1];
                    z1 += di * dn * c1[1];
                }
                unsigned wv = pk(z0, z1);
                if (h == 0) v.x = wv; else v.y = wv;
            }
            za[kp][ridx] = v;
        }
    }
    __syncthreads();

    float acc[2][8][4] = {};
#pragma unroll
    for (int ks = 0; ks < 2; ks++) {
        unsigned a[2][4];
#pragma unroll
        for (int i = 0; i < 2; i++) {
            int mt = wm * 2 + i;
            uint2 lo = za[ks * 8 + l4][mt * 8 + l8];
            uint2 hi = za[ks * 8 + 4 + l4][mt * 8 + l8];
            a[i][0] = lo.x; a[i][1] = lo.y; a[i][2] = hi.x; a[i][3] = hi.y;
        }
#pragma unroll
        for (int j = 0; j < 8; j++) {
            uint2 bh = wph[ks * 4 + l4][wn * 64 + j * 8 + l8];
            uint2 bl = wpl[ks * 4 + l4][wn * 64 + j * 8 + l8];
#pragma unroll
            for (int i = 0; i < 2; i++) {
                mma_bf16(acc[i][j], a[i][0], a[i][1], a[i][2], a[i][3], bh.x, bh.y);
                mma_bf16(acc[i][j], a[i][0], a[i][1], a[i][2], a[i][3], bl.x, bl.y);
            }
        }
    }

    // epilogue: relu(acc + bias) -> g_h1 bf16x2 words
    unsigned* h1w = (unsigned*)g_h1;
#pragma unroll
    for (int i = 0; i < 2; i++) {
#pragma unroll
        for (int j = 0; j < 8; j++) {
            int cb = wn * 64 + j * 8 + 2 * l4;
            float b0 = bsm[cb], b1 = bsm[cb + 1];
            int R0 = wm * 32 + i * 16 + l8;
            size_t node = (size_t)b * RT_ + p0 + R0;
            int cw = cb >> 1;
            h1w[node * 64 + cw] =
                pk(fmaxf(acc[i][j][0] + b0, 0.f), fmaxf(acc[i][j][1] + b1, 0.f));
            h1w[(node + 8) * 64 + cw] =
                pk(fmaxf(acc[i][j][2] + b0, 0.f), fmaxf(acc[i][j][3] + b1, 0.f));
        }
    }
}

// ---------------------------------------------------------------------------
// GCN2 (bf16 mma, split W): z2 = Anorm*h1 (stencil on bf16 h1), acc = z2@W2,
// epilogue relu + bias + per-batch column sums -> g_bsum.
// 128 rows x 128 cols, K=128 in 4 chunks of 32 (2 ksteps each). grid 4096.
// smem ~28KB -> 8 blocks/SM occupancy.
// ---------------------------------------------------------------------------
__global__ __launch_bounds__(256) void gcn2_kernel(const float* __restrict__ W,
                                                   const float* __restrict__ bias) {
    __shared__ uint2 za[16][68];
    __shared__ uint2 wph[8][132];
    __shared__ uint2 wpl[8][132];
    __shared__ float red[4][128];
    __shared__ float bsm[128];
    const int bx = blockIdx.x, b = bx >> 2, p0 = (bx & 3) << 7;
    const int tid = threadIdx.x, lane = tid & 31, warp = tid >> 5;
    const int wm = warp >> 1, wn = warp & 1, l4 = lane & 3, l8 = lane >> 2;

    if (tid < 128) bsm[tid] = bias[tid];

    float acc[2][8][4] = {};

    const unsigned* h1w = (const unsigned*)g_h1;
    const int fkp = tid & 15;          // k-pair 0..15 within chunk
    const int rb  = tid >> 4;          // ridx base 0..15

    for (int ch = 0; ch < 4; ch++) {
        const int k0 = ch * 32;
        if (ch) __syncthreads();
        // fill wph/wpl from W2 [128][128] chunk rows k0..k0+31
        {
            int n = tid & 127, fb = (tid >> 7) * 4;
#pragma unroll
            for (int i = 0; i < 4; i++) {
                int f = fb + i, ks = f >> 2, klo = f & 3;
                int ka = k0 + 2 * (ks * 8 + klo);
                unsigned hx, lx, hy, ly;
                pksplit(W[ka * HID_ + n], W[(ka + 1) * HID_ + n], hx, lx);
                pksplit(W[(ka + 8) * HID_ + n], W[(ka + 9) * HID_ + n], hy, ly);
                uint2 vh; vh.x = hx; vh.y = hy;
                uint2 vl; vl.x = lx; vl.y = ly;
                wph[f][n] = vh;
                wpl[f][n] = vl;
            }
        }
        // fill za: stencil over bf16 h1 words
        {
            const int cw = (k0 >> 1) + fkp;
#pragma unroll
            for (int i = 0; i < 4; i++) {
                int ridx = rb + 16 * i;
                int r0 = ((ridx >> 3) << 4) + (ridx & 7);
                uint2 v;
#pragma unroll
                for (int h = 0; h < 2; h++) {
                    int pp = p0 + r0 + h * 8;
                    size_t node = (size_t)b * RT_ + pp;
                    float di = (pp == 0 || pp == RT_ - 1) ? RS2 : RS3;
                    float2 c = upk(h1w[node * 64 + cw]);
                    float zx = di * di * c.x, zy = di * di * c.y;
                    if (pp > 0) {
                        float dp = (pp == 1) ? RS2 : RS3;
                        float2 t = upk(h1w[(node - 1) * 64 + cw]);
                        zx += di * dp * t.x; zy += di * dp * t.y;
                    }
                    if (pp < RT_ - 1) {
                        float dn = (pp == RT_ - 2) ? RS2 : RS3;
                        float2 t = upk(h1w[(node + 1) * 64 + cw]);
                        zx += di * dn * t.x; zy += di * dn * t.y;
                    }
                    unsigned wv = pk(zx, zy);
                    if (h == 0) v.x = wv; else v.y = wv;
                }
                za[fkp][ridx] = v;
            }
        }
        __syncthreads();

#pragma unroll
        for (int ks = 0; ks < 2; ks++) {
            unsigned a[2][4];
#pragma unroll
            for (int i = 0; i < 2; i++) {
                int mt = wm * 2 + i;
                uint2 lo = za[ks * 8 + l4][mt * 8 + l8];
                uint2 hi = za[ks * 8 + 4 + l4][mt * 8 + l8];
                a[i][0] = lo.x; a[i][1] = lo.y; a[i][2] = hi.x; a[i][3] = hi.y;
            }
#pragma unroll
            for (int j = 0; j < 8; j++) {
                uint2 bh = wph[ks * 4 + l4][wn * 64 + j * 8 + l8];
                uint2 bl = wpl[ks * 4 + l4][wn * 64 + j * 8 + l8];
#pragma unroll
                for (int i = 0; i < 2; i++) {
                    mma_bf16(acc[i][j], a[i][0], a[i][1], a[i][2], a[i][3], bh.x, bh.y);
                    mma_bf16(acc[i][j], a[i][0], a[i][1], a[i][2], a[i][3], bl.x, bl.y);
                }
            }
        }
    }

    // --- epilogue: relu(acc + bias), column sums, warp bfly reduce ---
    float s[8][2];
#pragma unroll
    for (int j = 0; j < 8; j++) {
        int colb = wn * 64 + j * 8 + 2 * l4;
        float b0v = bsm[colb], b1v = bsm[colb + 1];
        float s0 = 0.f, s1 = 0.f;
#pragma unroll
        for (int i = 0; i < 2; i++) {
            s0 += fmaxf(acc[i][j][0] + b0v, 0.f) + fmaxf(acc[i][j][2] + b0v, 0.f);
            s1 += fmaxf(acc[i][j][1] + b1v, 0.f) + fmaxf(acc[i][j][3] + b1v, 0.f);
        }
        s[j][0] = s0;
        s[j][1] = s1;
    }
#pragma unroll
    for (int j = 0; j < 8; j++)
#pragma unroll
        for (int lo = 0; lo < 2; lo++) {
            float v = s[j][lo];
            v += __shfl_xor_sync(0xffffffffu, v, 4);
            v += __shfl_xor_sync(0xffffffffu, v, 8);
            v += __shfl_xor_sync(0xffffffffu, v, 16);
            s[j][lo] = v;
        }
    if (lane < 4) {
#pragma unroll
        for (int j = 0; j < 8; j++)
#pragma unroll
            for (int lo = 0; lo < 2; lo++)
                red[wm][wn * 64 + j * 8 + 2 * lane + lo] = s[j][lo];
    }
    __syncthreads();

    if (tid < 128) {
        float t = red[0][tid] + red[1][tid] + red[2][tid] + red[3][tid];
        g_bsum[((size_t)b * 4 + (bx & 3)) * HID_ + tid] = t;
    }
}

// ---------------------------------------------------------------------------
// mean over RT (sum of 4 chunk partials / 512) then fc
// ---------------------------------------------------------------------------
__global__ void fc_kernel(const float* __restrict__ fw,
                          const float* __restrict__ fb,
                          float* __restrict__ out) {
    __shared__ float s[128];
    const int b = blockIdx.x, o = threadIdx.x;
    {
        float v0 = 0.f, v1 = 0.f;
#pragma unroll
        for (int c = 0; c < 4; c++) {
            v0 += g_bsum[((size_t)b * 4 + c) * HID_ + o];
            v1 += g_bsum[((size_t)b * 4 + c) * HID_ + o + 64];
        }
        s[o] = v0;
        s[o + 64] = v1;
    }
    __syncthreads();
    float a = 0.f;
#pragma unroll
    for (int k = 0; k < 128; k++) a += s[k] * fw[k * 64 + o];
    out[b * 64 + o] = a * (1.f / 512.f) + fb[o];
}

// ---------------------------------------------------------------------------
extern "C" void kernel_launch(void* const* d_in, const int* in_sizes, int n_in,
                              void* d_out, int out_size) {
    const float* x   = (const float*)d_in[0];
    const float* c1w = (const float*)d_in[1];
    const float* c1b = (const float*)d_in[2];
    const float* c2w = (const float*)d_in[3];
    const float* c2b = (const float*)d_in[4];
    const float* g1w = (const float*)d_in[5];
    const float* g1b = (const float*)d_in[6];
    const float* g2w = (const float*)d_in[7];
    const float* g2b = (const float*)d_in[8];
    const float* fw  = (const float*)d_in[9];
    const float* fb  = (const float*)d_in[10];
    float* out = (float*)d_out;

    conv1_kernel<<<dim3(B_, 8), 128>>>(x, c1w, c1b);
    conv2_kernel<<<dim3(B_, 4), 128>>>(c2w, c2b);
    gcn1_kernel<<<B_ * 4, 256>>>(g1w, g1b);
    gcn2_kernel<<<B_ * 4, 256>>>(g2w, g2b);
    fc_kernel<<<B_, 64>>>(fw, fb, out);
}